// round 11
// baseline (speedup 1.0000x reference)
#include <cuda_runtime.h>
#include <cstdint>

#define S_  128
#define E_  256
#define HD_ 512

// W stream: 512 chunks of 1024 floats (4KB). Chunk u = h*64 + c.
// c<32: KV chunk, k8 slice it=c, [slot0=K | slot1=V][n<64][kp<8]
// c>=32: QR chunk, it=c-32,    [slot0=Q | slot1=R][n<64][kp<8]
// pairing: kp=2t -> k=it*8+t ; kp=2t+1 -> k=it*8+t+4  (LDS.64 = b-frag pair)
__device__ __align__(16) float g_W[512 * 1024];

// smem floats: Xp[128][264] @0 | Wc 6x1024 ring @33792 | Ks[128][72] @39936 | Vt[64][136] @49152
#define SMEM_BYTES 231424

__device__ __forceinline__ float f2tf(float x) {
    uint32_t u; asm("cvt.rna.tf32.f32 %0, %1;" : "=r"(u) : "f"(x)); return __uint_as_float(u);
}
__device__ __forceinline__ uint32_t fau(float x) { return __float_as_uint(x); }

__device__ __forceinline__ void mma8(float c[4],
                                     uint32_t a0, uint32_t a1, uint32_t a2, uint32_t a3,
                                     uint32_t b0, uint32_t b1) {
    asm volatile(
        "mma.sync.aligned.m16n8k8.row.col.f32.tf32.tf32.f32 "
        "{%0,%1,%2,%3},{%4,%5,%6,%7},{%8,%9},{%0,%1,%2,%3};"
        : "+f"(c[0]), "+f"(c[1]), "+f"(c[2]), "+f"(c[3])
        : "r"(a0), "r"(a1), "r"(a2), "r"(a3), "r"(b0), "r"(b1));
}
__device__ __forceinline__ void cpa16(void* smem_dst, const void* gsrc) {
    uint32_t s = (uint32_t)__cvta_generic_to_shared(smem_dst);
    asm volatile("cp.async.cg.shared.global [%0], [%1], 16;" :: "r"(s), "l"(gsrc));
}

// ---------------------------------------------------------------------------
// Prep: round W to tf32, pack k8 chunks.
// ---------------------------------------------------------------------------
__global__ void prep_kernel(const float* __restrict__ wq, const float* __restrict__ wk,
                            const float* __restrict__ wv, const float* __restrict__ wr) {
    int idx = blockIdx.x * blockDim.x + threadIdx.x;
    if (idx >= 512 * 1024) return;
    int kp   = idx & 7;
    int n    = (idx >> 3) & 63;
    int slot = (idx >> 9) & 1;
    int c    = (idx >> 10) & 63;
    int h    = idx >> 16;
    int it = c & 31;
    int k = it * 8 + (kp >> 1) + (kp & 1) * 4;
    const float* W = (c < 32) ? (slot ? wv : wk) : (slot ? wr : wq);
    g_W[idx] = f2tf(W[(size_t)k * HD_ + h * 64 + n]);
}

// ---------------------------------------------------------------------------
// Fused MHA: one CTA per batch, 8 warps. 6-deep W ring, distance-5 prefetch.
// ---------------------------------------------------------------------------
__global__ void __launch_bounds__(256, 1)
mha_kernel(const float* __restrict__ X, float* __restrict__ Out) {
    extern __shared__ float sm[];
    int b = blockIdx.x, tid = threadIdx.x;
    int w = tid >> 5, lane = tid & 31, g = lane >> 2, t = lane & 3;
    int kvslot = w >> 2;               // warps 0-3: K, warps 4-7: V
    int r0kv = (w & 3) * 32;
    int r0 = w * 16;

    float* Wc = sm + 33792;            // 6 x 1024 floats
    float* Ks = sm + 39936;
    float* Vt = sm + 49152;

    // prologue: issue chunks 0..4 (one 16B cp.async per thread per chunk)
#pragma unroll
    for (int p = 0; p < 5; ++p) {
        cpa16((char*)Wc + p * 4096 + tid * 16, (const char*)g_W + (size_t)p * 4096 + tid * 16);
        asm volatile("cp.async.commit_group;" ::: "memory");
    }

    // Stage X -> Xp (tf32 round + k-pairing, stride 264) while chunks fly.
    const float* Xg = X + (size_t)b * S_ * E_;
    for (int i = tid; i < S_ * E_ / 4; i += 256) {
        int r = i >> 6, c4 = (i & 63) * 4;
        float4 v = *(const float4*)&Xg[r * E_ + c4];
        float vv[4] = {v.x, v.y, v.z, v.w};
#pragma unroll
        for (int e = 0; e < 4; ++e) {
            int col = c4 + e, kt = col >> 3, q = col & 7;
            int kp = kt * 8 + ((q < 4) ? 2 * q : 2 * (q - 4) + 1);
            sm[r * 264 + kp] = f2tf(vv[e]);
        }
    }

    const float L2E = 1.4426950408889634f;

    for (int h = 0; h < 8; ++h) {
        // ========== Phase 1: K (warps 0-3) & V (warps 4-7), Mt=2 (32 rows) ==========
        {
            float kv[2][8][4];
#pragma unroll
            for (int m = 0; m < 2; ++m)
#pragma unroll
                for (int j = 0; j < 8; ++j)
#pragma unroll
                    for (int i = 0; i < 4; ++i) kv[m][j][i] = 0.0f;

            for (int c = 0; c < 32; ++c) {
                int u = h * 64 + c;
                asm volatile("cp.async.wait_group 4;" ::: "memory");   // chunk u landed (mine)
                __syncthreads();                                       // all copies of u visible; buf (u+5)%6 free
                if (u + 5 < 512) {
                    cpa16((char*)Wc + ((u + 5) % 6) * 4096 + tid * 16,
                          (const char*)g_W + (size_t)(u + 5) * 4096 + tid * 16);
                    asm volatile("cp.async.commit_group;" ::: "memory");
                }
                const float* Wb = Wc + (u % 6) * 1024 + kvslot * 512;
                float2 Bf[8];
#pragma unroll
                for (int j = 0; j < 8; ++j)
                    Bf[j] = *(const float2*)&Wb[(j * 8 + g) * 8 + 2 * t];
#pragma unroll
                for (int m = 0; m < 2; ++m) {
                    int rr = r0kv + m * 16;
                    float2 alo = *(const float2*)&sm[(rr + g) * 264 + c * 8 + 2 * t];
                    float2 ahi = *(const float2*)&sm[(rr + g + 8) * 264 + c * 8 + 2 * t];
                    uint32_t a0 = fau(alo.x), a1 = fau(ahi.x), a2 = fau(alo.y), a3 = fau(ahi.y);
#pragma unroll
                    for (int j = 0; j < 8; ++j)
                        mma8(kv[m][j], a0, a1, a2, a3, fau(Bf[j].x), fau(Bf[j].y));
                }
            }
            if (kvslot == 0) {
#pragma unroll
                for (int m = 0; m < 2; ++m)
#pragma unroll
                    for (int j = 0; j < 8; ++j) {
                        *(float2*)&Ks[(r0kv + 16 * m + g) * 72 + j * 8 + 2 * t] =
                            make_float2(f2tf(kv[m][j][0]), f2tf(kv[m][j][1]));
                        *(float2*)&Ks[(r0kv + 16 * m + g + 8) * 72 + j * 8 + 2 * t] =
                            make_float2(f2tf(kv[m][j][2]), f2tf(kv[m][j][3]));
                    }
            } else {
#pragma unroll
                for (int m = 0; m < 2; ++m)
#pragma unroll
                    for (int j = 0; j < 8; ++j) {
                        Vt[(j * 8 + 2 * t) * 136 + r0kv + 16 * m + g]         = f2tf(kv[m][j][0]);
                        Vt[(j * 8 + 2 * t + 1) * 136 + r0kv + 16 * m + g]     = f2tf(kv[m][j][1]);
                        Vt[(j * 8 + 2 * t) * 136 + r0kv + 16 * m + g + 8]     = f2tf(kv[m][j][2]);
                        Vt[(j * 8 + 2 * t + 1) * 136 + r0kv + 16 * m + g + 8] = f2tf(kv[m][j][3]);
                    }
            }
        }

        // ========== Phase 2: Q+R merged (per-warp 16 rows, n=128) ==========
        float qf[8][4], rf[8][4];
#pragma unroll
        for (int j = 0; j < 8; ++j)
#pragma unroll
            for (int i = 0; i < 4; ++i) { qf[j][i] = 0.0f; rf[j][i] = 0.0f; }

        for (int c = 32; c < 64; ++c) {
            int u = h * 64 + c;
            asm volatile("cp.async.wait_group 4;" ::: "memory");
            __syncthreads();
            if (u + 5 < 512) {
                cpa16((char*)Wc + ((u + 5) % 6) * 4096 + tid * 16,
                      (const char*)g_W + (size_t)(u + 5) * 4096 + tid * 16);
                asm volatile("cp.async.commit_group;" ::: "memory");
            }
            const float* Wb = Wc + (u % 6) * 1024;
            int it = c - 32;
            float2 alo = *(const float2*)&sm[(r0 + g) * 264 + it * 8 + 2 * t];
            float2 ahi = *(const float2*)&sm[(r0 + g + 8) * 264 + it * 8 + 2 * t];
            uint32_t a0 = fau(alo.x), a1 = fau(ahi.x), a2 = fau(alo.y), a3 = fau(ahi.y);
#pragma unroll
            for (int j = 0; j < 8; ++j) {
                float2 bq = *(const float2*)&Wb[(j * 8 + g) * 8 + 2 * t];
                mma8(qf[j], a0, a1, a2, a3, fau(bq.x), fau(bq.y));
                float2 br = *(const float2*)&Wb[512 + (j * 8 + g) * 8 + 2 * t];
                mma8(rf[j], a0, a1, a2, a3, fau(br.x), fau(br.y));
            }
        }

        // round Q to tf32
#pragma unroll
        for (int j = 0; j < 8; ++j)
#pragma unroll
            for (int i = 0; i < 4; ++i) qf[j][i] = f2tf(qf[j][i]);

        __syncthreads();   // Ks/Vt complete before attention reads

        // ---- scores = Q @ K^T (Q C-frags reused as A via k-order permutation) ----
        float s[16][4];
#pragma unroll
        for (int n = 0; n < 16; ++n)
#pragma unroll
            for (int i = 0; i < 4; ++i) s[n][i] = 0.0f;
#pragma unroll
        for (int jq = 0; jq < 8; ++jq) {
            uint32_t a0 = fau(qf[jq][0]);
            uint32_t a1 = fau(qf[jq][2]);
            uint32_t a2 = fau(qf[jq][1]);
            uint32_t a3 = fau(qf[jq][3]);
#pragma unroll
            for (int n = 0; n < 16; ++n) {
                float2 bb = *(const float2*)&Ks[(n * 8 + g) * 72 + jq * 8 + 2 * t];
                mma8(s[n], a0, a1, a2, a3, fau(bb.x), fau(bb.y));
            }
        }

        // ---- softmax (rows r0+g / r0+g+8) ----
        float m0 = -1e30f, m1 = -1e30f;
#pragma unroll
        for (int n = 0; n < 16; ++n) {
            m0 = fmaxf(m0, fmaxf(s[n][0], s[n][1]));
            m1 = fmaxf(m1, fmaxf(s[n][2], s[n][3]));
        }
        m0 = fmaxf(m0, __shfl_xor_sync(0xffffffffu, m0, 1));
        m0 = fmaxf(m0, __shfl_xor_sync(0xffffffffu, m0, 2));
        m1 = fmaxf(m1, __shfl_xor_sync(0xffffffffu, m1, 1));
        m1 = fmaxf(m1, __shfl_xor_sync(0xffffffffu, m1, 2));

        float sum0 = 0.0f, sum1 = 0.0f;
#pragma unroll
        for (int n = 0; n < 16; ++n) {
            float p0 = exp2f((s[n][0] - m0) * L2E);
            float p1 = exp2f((s[n][1] - m0) * L2E);
            float p2 = exp2f((s[n][2] - m1) * L2E);
            float p3 = exp2f((s[n][3] - m1) * L2E);
            sum0 += p0 + p1;
            sum1 += p2 + p3;
            s[n][0] = f2tf(p0); s[n][1] = f2tf(p1);
            s[n][2] = f2tf(p2); s[n][3] = f2tf(p3);
        }
        sum0 += __shfl_xor_sync(0xffffffffu, sum0, 1);
        sum0 += __shfl_xor_sync(0xffffffffu, sum0, 2);
        sum1 += __shfl_xor_sync(0xffffffffu, sum1, 1);
        sum1 += __shfl_xor_sync(0xffffffffu, sum1, 2);
        float sc0 = 1.0f / sum0, sc1 = 1.0f / sum1;

        // ---- O = P @ V ----
        float o[8][4];
#pragma unroll
        for (int j = 0; j < 8; ++j)
#pragma unroll
            for (int i = 0; i < 4; ++i) o[j][i] = 0.0f;
#pragma unroll
        for (int js = 0; js < 16; ++js) {
            uint32_t a0 = fau(s[js][0]);
            uint32_t a1 = fau(s[js][2]);
            uint32_t a2 = fau(s[js][1]);
            uint32_t a3 = fau(s[js][3]);
#pragma unroll
            for (int j = 0; j < 8; ++j) {
                float2 bb = *(const float2*)&Vt[(j * 8 + g) * 136 + js * 8 + 2 * t];
                mma8(o[j], a0, a1, a2, a3, fau(bb.x), fau(bb.y));
            }
        }

        // ---- epilogue: out = relu(O/rowsum + R) ----
        size_t ob = (size_t)b * S_ * HD_ + (size_t)h * 64;
#pragma unroll
        for (int j = 0; j < 8; ++j) {
            float2 lo, hi;
            lo.x = fmaxf(o[j][0] * sc0 + rf[j][0], 0.0f);
            lo.y = fmaxf(o[j][1] * sc0 + rf[j][1], 0.0f);
            hi.x = fmaxf(o[j][2] * sc1 + rf[j][2], 0.0f);
            hi.y = fmaxf(o[j][3] * sc1 + rf[j][3], 0.0f);
            *(float2*)&Out[ob + (size_t)(r0 + g) * HD_ + j * 8 + 2 * t] = lo;
            *(float2*)&Out[ob + (size_t)(r0 + g + 8) * HD_ + j * 8 + 2 * t] = hi;
        }
        __syncthreads();   // Ks/Vt protected before next head overwrites
    }
}

extern "C" void kernel_launch(void* const* d_in, const int* in_sizes, int n_in,
                              void* d_out, int out_size) {
    const float* x  = (const float*)d_in[0];
    const float* wq = (const float*)d_in[1];
    const float* wk = (const float*)d_in[2];
    const float* wv = (const float*)d_in[3];
    const float* wr = (const float*)d_in[4];
    float* out = (float*)d_out;

    cudaFuncSetAttribute(mha_kernel, cudaFuncAttributeMaxDynamicSharedMemorySize, SMEM_BYTES);
    prep_kernel<<<2048, 256>>>(wq, wk, wv, wr);
    mha_kernel<<<1024, 256, SMEM_BYTES>>>(x, out);
}